// round 14
// baseline (speedup 1.0000x reference)
#include <cuda_runtime.h>
#include <cstdint>

// Problem: B=8, S=128, V=32000, E=768
// input:  one-hot [B,S,V] f32  (exactly one 1.0 per row, rest 0.0)
// weight: [V,E] f32
// out:    [B,S,E] f32 = weight[argnonzero(input[b,s,:]), :]
//
// TMA-path scan: each CTA issues ONE cp.async.bulk (global->SMEM, 16000 B
// segment) through the async proxy, bypassing the ~248-wavefront L1tex queue
// that caps LDG-path in-flight bytes at ~31 KB/SM. With 8 CTAs/SM the TMA
// path keeps ~128 KB/SM in flight. Threads scan SMEM via LDS, detect the 1.0
// with raw-bit OR + __syncthreads_or, and the finding CTA gathers the row.

#define NROWS    1024
#define ROW_F4   8000          // float4 per row
#define SEGS     8
#define SEG_F4   1000          // float4 per segment (16000 B)
#define SEG_B    16000
#define VEC_E    192           // float4 per output row
#define THREADS  256

__device__ __forceinline__ uint32_t smem_u32(const void* p) {
    uint32_t a;
    asm("{ .reg .u64 t; cvta.to.shared.u64 t, %1; cvt.u32.u64 %0, t; }"
        : "=r"(a) : "l"(p));
    return a;
}

__global__ __launch_bounds__(THREADS, 8)
void onehot_embed_kernel(const float4* __restrict__ oh,
                         const float4* __restrict__ w,
                         float4* __restrict__ out)
{
    __shared__ alignas(128) uint4 tile[SEG_F4];   // 16000 B
    __shared__ alignas(8) unsigned long long mbar;
    __shared__ int s_idx;

    const int unit = blockIdx.x;          // 8192 CTAs
    const int row  = unit >> 3;
    const int seg  = unit & 7;
    const int tid  = threadIdx.x;

    const char* src = (const char*)(oh + (size_t)row * ROW_F4 + seg * SEG_F4);
    const uint32_t mbar_a = smem_u32(&mbar);
    const uint32_t tile_a = smem_u32(tile);

    if (tid == 0) {
        asm volatile("mbarrier.init.shared.b64 [%0], %1;"
                     :: "r"(mbar_a), "r"(1u) : "memory");
    }
    __syncthreads();

    if (tid == 0) {
        asm volatile("mbarrier.arrive.expect_tx.shared.b64 _, [%0], %1;"
                     :: "r"(mbar_a), "r"((unsigned)SEG_B) : "memory");
        asm volatile("cp.async.bulk.shared::cta.global.mbarrier::complete_tx::bytes "
                     "[%0], [%1], %2, [%3];"
                     :: "r"(tile_a), "l"(src), "r"((unsigned)SEG_B), "r"(mbar_a)
                     : "memory");
    }

    // ---- wait for TMA completion (acquire so LDS below is ordered) ----
    {
        unsigned done;
        asm volatile(
            "{\n\t.reg .pred p;\n\t"
            "mbarrier.try_wait.parity.acquire.cta.shared::cta.b64 p, [%1], %2;\n\t"
            "selp.b32 %0, 1, 0, p;\n\t}"
            : "=r"(done) : "r"(mbar_a), "r"(0u) : "memory");
        if (!done) {
            asm volatile(
                "{\n\t.reg .pred P1;\n\t"
                "W_%=:\n\t"
                "mbarrier.try_wait.parity.acquire.cta.shared::cta.b64 P1, [%0], %1, 0x989680;\n\t"
                "@P1 bra.uni D_%=;\n\t"
                "bra.uni W_%=;\n\t"
                "D_%=:\n\t}"
                :: "r"(mbar_a), "r"(0u) : "memory");
        }
    }

    // ---- scan SMEM: 1000 uint4 = 3*256 + 232 per thread ----
    uint4 v0 = tile[tid];
    uint4 v1 = tile[tid + 256];
    uint4 v2 = tile[tid + 512];
    uint4 v3 = make_uint4(0u, 0u, 0u, 0u);
    if (tid < SEG_F4 - 768) v3 = tile[tid + 768];

    unsigned m0 = v0.x | v0.y | v0.z | v0.w;
    unsigned m1 = v1.x | v1.y | v1.z | v1.w;
    unsigned m2 = v2.x | v2.y | v2.z | v2.w;
    unsigned m3 = v3.x | v3.y | v3.z | v3.w;
    unsigned m  = m0 | m1 | m2 | m3;

    const int blockFound = __syncthreads_or(m != 0u);
    if (!blockFound) return;              // common path: 511/512 CTAs exit here

    // ---- rare path: exact integer index recovery ----
    if (m != 0u) {                        // exactly one thread in the CTA
        int k;  uint4 vs;
        if      (m0) { k = 0; vs = v0; }
        else if (m1) { k = 1; vs = v1; }
        else if (m2) { k = 2; vs = v2; }
        else         { k = 3; vs = v3; }
        int c = vs.x ? 0 : vs.y ? 1 : vs.z ? 2 : 3;
        s_idx = 4 * (seg * SEG_F4 + tid + k * 256) + c;
    }
    __syncthreads();

    // ---- gather weight row -> out row (192 float4) ----
    const int idx = s_idx;
    const float4* __restrict__ wr = w   + (size_t)idx * VEC_E;
    float4*       __restrict__ o  = out + (size_t)row * VEC_E;
    if (tid < VEC_E)
        o[tid] = __ldg(&wr[tid]);
}

extern "C" void kernel_launch(void* const* d_in, const int* in_sizes, int n_in,
                              void* d_out, int out_size)
{
    // metadata order: input (one-hot), weight. Defensive swap by size.
    const float4* oh = (const float4*)d_in[0];
    const float4* w  = (const float4*)d_in[1];
    if (n_in >= 2 && in_sizes[0] < in_sizes[1]) {  // weight (24.6M) < one-hot (32.8M)
        oh = (const float4*)d_in[1];
        w  = (const float4*)d_in[0];
    }
    onehot_embed_kernel<<<NROWS * SEGS, THREADS>>>(oh, w, (float4*)d_out);
}

// round 15
// speedup vs baseline: 1.0122x; 1.0122x over previous
#include <cuda_runtime.h>
#include <cstdint>

// Problem: B=8, S=128, V=32000, E=768
// input:  one-hot [B,S,V] f32  (exactly one 1.0 per row, rest 0.0)
// weight: [V,E] f32
// out:    [B,S,E] f32 = weight[argnonzero(input[b,s,:]), :]
//
// Converged design (best measured): warp-autonomous minimal-tail scan.
// Each warp owns a 125-float4 (2 KB) segment. Common path = 4x LDG.128 +
// raw-bit OR + one ballot, then exit. The 1-in-512 warp holding the 1.0
// recovers the index with exact integer ops (ffs + select + shfl) and
// gathers the weight row. Default cache policy (no __ldcs) — final probe.

#define NROWS    1024
#define VEC_V    8000         // float4 per row
#define WSEG     125          // float4 per warp segment (2 KB)
#define WPB      8            // warps per block
#define THREADS  (WPB * 32)
#define VEC_E    192          // float4 per output row

__global__ __launch_bounds__(THREADS, 8)
void onehot_embed_kernel(const float4* __restrict__ oh,
                         const float4* __restrict__ w,
                         float4* __restrict__ out)
{
    const int unit  = blockIdx.x;          // 8192 CTAs
    const int row   = unit >> 3;
    const int wblk  = unit & 7;
    const int warp  = threadIdx.x >> 5;
    const int lane  = threadIdx.x & 31;
    const int wseg  = wblk * WPB + warp;   // 0..63 within row

    const float4* __restrict__ r = oh + (size_t)row * VEC_V + wseg * WSEG;

    // ---- front-batched loads: 3 unconditional + 1 predicated (125 = 3*32+29)
    const int i3 = lane + 96;
    float4 v0 = r[lane];
    float4 v1 = r[lane + 32];
    float4 v2 = r[lane + 64];
    float4 v3 = make_float4(0.f, 0.f, 0.f, 0.f);
    if (i3 < WSEG) v3 = r[i3];

    // ---- detection only: raw-bit OR per load, then per-lane ----
    unsigned m0 = __float_as_uint(v0.x) | __float_as_uint(v0.y) | __float_as_uint(v0.z) | __float_as_uint(v0.w);
    unsigned m1 = __float_as_uint(v1.x) | __float_as_uint(v1.y) | __float_as_uint(v1.z) | __float_as_uint(v1.w);
    unsigned m2 = __float_as_uint(v2.x) | __float_as_uint(v2.y) | __float_as_uint(v2.z) | __float_as_uint(v2.w);
    unsigned m3 = __float_as_uint(v3.x) | __float_as_uint(v3.y) | __float_as_uint(v3.z) | __float_as_uint(v3.w);
    unsigned m  = m0 | m1 | m2 | m3;

    unsigned found = __ballot_sync(0xffffffffu, m != 0u);
    if (found == 0u) return;               // common path: exit, ~30 cyc tail

    // ---- rare path (1 warp in 512): exact integer index recovery ----
    const int src = __ffs(found) - 1;      // owning lane

    // which of the 4 loads holds it (valid only in owning lane)
    int k;  float4 vs;
    if      (m0) { k = 0; vs = v0; }
    else if (m1) { k = 1; vs = v1; }
    else if (m2) { k = 2; vs = v2; }
    else         { k = 3; vs = v3; }
    // which component
    int c = __float_as_uint(vs.x) ? 0 :
            __float_as_uint(vs.y) ? 1 :
            __float_as_uint(vs.z) ? 2 : 3;

    const int gbase = wseg * WSEG;         // float4 base within row
    int idx_local = 4 * (gbase + lane + k * 32) + c;
    int idx = __shfl_sync(0xffffffffu, idx_local, src);

    // ---- gather weight row -> out row (192 float4, 6 per lane) ----
    const float4* __restrict__ wr = w   + (size_t)idx * VEC_E;
    float4*       __restrict__ o  = out + (size_t)row * VEC_E;
    #pragma unroll
    for (int j = lane; j < VEC_E; j += 32)
        o[j] = __ldg(&wr[j]);
}

extern "C" void kernel_launch(void* const* d_in, const int* in_sizes, int n_in,
                              void* d_out, int out_size)
{
    // metadata order: input (one-hot), weight. Defensive swap by size.
    const float4* oh = (const float4*)d_in[0];
    const float4* w  = (const float4*)d_in[1];
    if (n_in >= 2 && in_sizes[0] < in_sizes[1]) {  // weight (24.6M) < one-hot (32.8M)
        oh = (const float4*)d_in[1];
        w  = (const float4*)d_in[0];
    }
    onehot_embed_kernel<<<NROWS * 8, THREADS>>>(oh, w, (float4*)d_out);
}

// round 16
// speedup vs baseline: 1.0807x; 1.0677x over previous
#include <cuda_runtime.h>
#include <cstdint>

// Problem: B=8, S=128, V=32000, E=768
// input:  one-hot [B,S,V] f32  (exactly one 1.0 per row, rest 0.0)
// weight: [V,E] f32
// out:    [B,S,E] f32 = weight[argnonzero(input[b,s,:]), :]
//
// FINAL (converged): warp-autonomous minimal-tail scan, DRAM-roofline-bound.
// Measured: ~24.1 us kernel, 5.7-5.8 TB/s (~72% HBM spec) -- the practical
// ceiling for this read-dominant stream, invariant across LDG/TMA paths.
// Each warp owns a 125-float4 (2 KB) segment. Common path = 4x LDG.128
// (evict-first) + raw-bit OR + one ballot, then exit. The 1-in-512 warp
// holding the 1.0 recovers the index exactly in integers (ffs + select +
// shfl) and gathers the 3 KB weight row itself. No smem, no barriers.

#define NROWS    1024
#define VEC_V    8000         // float4 per row
#define WSEG     125          // float4 per warp segment (2 KB)
#define WPB      8            // warps per block
#define THREADS  (WPB * 32)
#define VEC_E    192          // float4 per output row

__global__ __launch_bounds__(THREADS, 8)
void onehot_embed_kernel(const float4* __restrict__ oh,
                         const float4* __restrict__ w,
                         float4* __restrict__ out)
{
    const int unit  = blockIdx.x;          // 8192 CTAs
    const int row   = unit >> 3;
    const int wblk  = unit & 7;
    const int warp  = threadIdx.x >> 5;
    const int lane  = threadIdx.x & 31;
    const int wseg  = wblk * WPB + warp;   // 0..63 within row

    const float4* __restrict__ r = oh + (size_t)row * VEC_V + wseg * WSEG;

    // ---- front-batched loads: 3 unconditional + 1 predicated (125 = 3*32+29)
    const int i3 = lane + 96;
    float4 v0 = __ldcs(&r[lane]);
    float4 v1 = __ldcs(&r[lane + 32]);
    float4 v2 = __ldcs(&r[lane + 64]);
    float4 v3 = make_float4(0.f, 0.f, 0.f, 0.f);
    if (i3 < WSEG) v3 = __ldcs(&r[i3]);

    // ---- detection only: raw-bit OR per load, then per-lane ----
    unsigned m0 = __float_as_uint(v0.x) | __float_as_uint(v0.y) | __float_as_uint(v0.z) | __float_as_uint(v0.w);
    unsigned m1 = __float_as_uint(v1.x) | __float_as_uint(v1.y) | __float_as_uint(v1.z) | __float_as_uint(v1.w);
    unsigned m2 = __float_as_uint(v2.x) | __float_as_uint(v2.y) | __float_as_uint(v2.z) | __float_as_uint(v2.w);
    unsigned m3 = __float_as_uint(v3.x) | __float_as_uint(v3.y) | __float_as_uint(v3.z) | __float_as_uint(v3.w);
    unsigned m  = m0 | m1 | m2 | m3;

    unsigned found = __ballot_sync(0xffffffffu, m != 0u);
    if (found == 0u) return;               // common path: exit, ~30 cyc tail

    // ---- rare path (1 warp in 512): exact integer index recovery ----
    const int src = __ffs(found) - 1;      // owning lane

    // which of the 4 loads holds it (valid only in owning lane)
    int k;  float4 vs;
    if      (m0) { k = 0; vs = v0; }
    else if (m1) { k = 1; vs = v1; }
    else if (m2) { k = 2; vs = v2; }
    else         { k = 3; vs = v3; }
    // which component
    int c = __float_as_uint(vs.x) ? 0 :
            __float_as_uint(vs.y) ? 1 :
            __float_as_uint(vs.z) ? 2 : 3;

    const int gbase = wseg * WSEG;         // float4 base within row
    int idx_local = 4 * (gbase + lane + k * 32) + c;
    int idx = __shfl_sync(0xffffffffu, idx_local, src);

    // ---- gather weight row -> out row (192 float4, 6 per lane) ----
    const float4* __restrict__ wr = w   + (size_t)idx * VEC_E;
    float4*       __restrict__ o  = out + (size_t)row * VEC_E;
    #pragma unroll
    for (int j = lane; j < VEC_E; j += 32)
        o[j] = __ldg(&wr[j]);
}

extern "C" void kernel_launch(void* const* d_in, const int* in_sizes, int n_in,
                              void* d_out, int out_size)
{
    // metadata order: input (one-hot), weight. Defensive swap by size.
    const float4* oh = (const float4*)d_in[0];
    const float4* w  = (const float4*)d_in[1];
    if (n_in >= 2 && in_sizes[0] < in_sizes[1]) {  // weight (24.6M) < one-hot (32.8M)
        oh = (const float4*)d_in[1];
        w  = (const float4*)d_in[0];
    }
    onehot_embed_kernel<<<NROWS * 8, THREADS>>>(oh, w, (float4*)d_out);
}